// round 16
// baseline (speedup 1.0000x reference)
#include <cuda_runtime.h>
#include <cuda_bf16.h>

typedef unsigned long long ull;

// Problem constants (fixed by the reference)
#define N_BATCH 128
#define T_STEPS 128
#define IN_F    2048
#define OUT_F   2048
#define M_TOTAL (N_BATCH * T_STEPS)   // 16384
// Power-of-two k-blocking: blocks [0,512),[512,1024),[1024,1536),[1536,2048),
// folded sequentially ascending. Ref=kc512 is the unique hypothesis predicting
// the two lowest measured flip counts (kc504 -> F=10 via shared first block,
// kc1024 -> F=15 via nested-block correlation).
#define KC      512

// Scratch for membrane potentials: [M_TOTAL, OUT_F] fp32 = 134 MB.
__device__ float g_pot[(size_t)M_TOTAL * OUT_F];

// ---- packed dual-fp32 helpers (PROVEN bitwise == two scalar fp32 ops: R4==R5)
__device__ __forceinline__ ull pack2(float x) {
    ull r;
    asm("mov.b64 %0, {%1, %1};" : "=l"(r) : "f"(x));
    return r;
}
__device__ __forceinline__ void ffma2(ull& acc, ull a, ull b) {
    asm("fma.rn.f32x2 %0, %1, %2, %0;" : "+l"(acc) : "l"(a), "l"(b));
}
__device__ __forceinline__ ull fadd2(ull a, ull b) {
    ull r;
    asm("add.rn.f32x2 %0, %1, %2;" : "=l"(r) : "l"(a), "l"(b));
    return r;
}
__device__ __forceinline__ float lo32(ull v) { return __uint_as_float((unsigned)v); }
__device__ __forceinline__ float hi32(ull v) { return __uint_as_float((unsigned)(v >> 32)); }

// ---------------------------------------------------------------------------
// GEMM, reference-ordering replica:
//   pot[m,o] = fl( (((S0 + S1) + S2) + S3) + fl(bias[o] * 2^-7) )
//   Sb = strict ascending-k serial fp32 FMA chain over k-block b,
//   blocks: [0,512), [512,1024), [1024,1536), [1536,2048).
// 128x128 CTA tile, BK=8 (divides 512), 256 threads, 8x8 micro-tile
// computed as 8x4 f32x2 pairs over adjacent o columns (FFMA2 bitwise-safe).
// ---------------------------------------------------------------------------
#define BM 128
#define BN 128
#define BKT 8
#define SPAD 132

__global__ __launch_bounds__(256, 1)
void spike_gemm_f32x2_kernel(const float* __restrict__ A,
                             const float* __restrict__ W,
                             const float* __restrict__ bias)
{
    __shared__ ull   As2[BKT][BM];    // [k][m], duplicated pairs {a,a}
    __shared__ float Bs[BKT][SPAD];   // [k][o]

    const int tid = threadIdx.x;
    const int m0  = blockIdx.y * BM;
    const int o0  = blockIdx.x * BN;

    const int ty = tid >> 4;   // 0..15 -> rows m0 + ty*8 .. +7
    const int tx = tid & 15;   // 0..15 -> cols o0 + tx*8 .. +7

    ull tot[8][4];   // packed pairs over columns: lane0 = even col
    ull blk[8][4];
#pragma unroll
    for (int r = 0; r < 8; r++)
#pragma unroll
        for (int j = 0; j < 4; j++) { tot[r][j] = 0ull; blk[r][j] = 0ull; }

    // Tile loads: 128 rows x 8 cols = 256 float4 per matrix; one per thread.
    const int lrow = tid >> 1;          // 0..127
    const int lc4  = (tid & 1) << 2;    // 0 or 4

    const float* pA = &A[(size_t)(m0 + lrow) * IN_F + lc4];
    const float* pW = &W[(size_t)(o0 + lrow) * IN_F + lc4];

    // Prefetch first tile into registers
    float4 va = *reinterpret_cast<const float4*>(pA);
    float4 vb = *reinterpret_cast<const float4*>(pW);

    for (int k0 = 0; k0 < IN_F; k0 += BKT) {
        // Stage current tile to shared (A duplicated into pair lanes)
        As2[lc4 + 0][lrow] = pack2(va.x);
        As2[lc4 + 1][lrow] = pack2(va.y);
        As2[lc4 + 2][lrow] = pack2(va.z);
        As2[lc4 + 3][lrow] = pack2(va.w);
        Bs[lc4 + 0][lrow] = vb.x;
        Bs[lc4 + 1][lrow] = vb.y;
        Bs[lc4 + 2][lrow] = vb.z;
        Bs[lc4 + 3][lrow] = vb.w;
        __syncthreads();

        // Prefetch next tile (overlaps with compute below)
        if (k0 + BKT < IN_F) {
            va = *reinterpret_cast<const float4*>(pA + k0 + BKT);
            vb = *reinterpret_cast<const float4*>(pW + k0 + BKT);
        }

#pragma unroll
        for (int kk = 0; kk < BKT; kk++) {
            ull b2[4];
            const ull* pb = reinterpret_cast<const ull*>(&Bs[kk][tx * 8]);
#pragma unroll
            for (int j = 0; j < 4; j++) b2[j] = pb[j];

            ull a2[8];
#pragma unroll
            for (int r = 0; r < 8; r++) a2[r] = As2[kk][ty * 8 + r];

#pragma unroll
            for (int r = 0; r < 8; r++)
#pragma unroll
                for (int j = 0; j < 4; j++)
                    ffma2(blk[r][j], a2[r], b2[j]);
        }
        __syncthreads();

        // Fold at kc-block boundaries (512, 1024, 1536) and at the end (2048).
        // fl(0 + S0) == S0 exactly, so unconditional += replicates C = S0.
        const int kend = k0 + BKT;
        if ((kend & (KC - 1)) == 0) {
#pragma unroll
            for (int r = 0; r < 8; r++)
#pragma unroll
                for (int j = 0; j < 4; j++) { tot[r][j] = fadd2(tot[r][j], blk[r][j]); blk[r][j] = 0ull; }
        }
    }

    // Epilogue: pot = fl(tot + fl(bias * 2^-7))   (2^-7 scale exact)
    const float inv_t = 1.0f / (float)T_STEPS;
#pragma unroll
    for (int r = 0; r < 8; r++) {
        const size_t base = (size_t)(m0 + ty * 8 + r) * OUT_F + o0 + tx * 8;
        float v[8];
#pragma unroll
        for (int j = 0; j < 4; j++) {
            v[2 * j + 0] = lo32(tot[r][j]) + bias[o0 + tx * 8 + 2 * j + 0] * inv_t;
            v[2 * j + 1] = hi32(tot[r][j]) + bias[o0 + tx * 8 + 2 * j + 1] * inv_t;
        }
#pragma unroll
        for (int c = 0; c < 8; c += 4) {
            float4 s;
            s.x = v[c + 0]; s.y = v[c + 1]; s.z = v[c + 2]; s.w = v[c + 3];
            *reinterpret_cast<float4*>(&g_pot[base + c]) = s;
        }
    }
}

// ---------------------------------------------------------------------------
// LIF scan: bit-exact fp32 replica of the reference recurrence.
//   mem = fl(fl(mem + pot) - spike) ;  spike = (mem >= 1.0f)
// ---------------------------------------------------------------------------
__global__ __launch_bounds__(256)
void lif_scan_kernel(const float* __restrict__ pot, float* __restrict__ out)
{
    const int idx = blockIdx.x * blockDim.x + threadIdx.x;  // n*OUT_F + o
    const int n = idx >> 11;
    const int o = idx & (OUT_F - 1);

    const float* p = pot + (size_t)n * T_STEPS * OUT_F + o;
    float*       q = out + (size_t)n * T_STEPS * OUT_F + o;

    float mem = 0.0f;
    float spike = 0.0f;
#pragma unroll 8
    for (int t = 0; t < T_STEPS; t++) {
        mem = (mem + p[(size_t)t * OUT_F]) - spike;
        spike = (mem >= 1.0f) ? 1.0f : 0.0f;
        q[(size_t)t * OUT_F] = spike;
    }
}

// ---------------------------------------------------------------------------
// Launch
// ---------------------------------------------------------------------------
extern "C" void kernel_launch(void* const* d_in, const int* in_sizes, int n_in,
                              void* d_out, int out_size)
{
    const float* spike_in = (const float*)d_in[0];  // [128,128,2048]
    const float* weight   = (const float*)d_in[1];  // [2048,2048]
    const float* bias     = (const float*)d_in[2];  // [2048]
    float* out = (float*)d_out;                     // [128,128,2048]

    float* pot;
    cudaGetSymbolAddress((void**)&pot, g_pot);

    dim3 ggrid(OUT_F / BN, M_TOTAL / BM);   // (16, 128)
    spike_gemm_f32x2_kernel<<<ggrid, 256>>>(spike_in, weight, bias);

    const int total = N_BATCH * OUT_F;      // 262144 trajectories
    lif_scan_kernel<<<total / 256, 256>>>(pot, out);
}